// round 10
// baseline (speedup 1.0000x reference)
#include <cuda_runtime.h>

// StackMemory — warp-specialized, load-balanced (R9 form + tail rebalance).
//
// Reference scan only writes stack row 0 and reads row 1 (always zero), so:
//   out[0, t, 0, h] = softmax0(hs[t]·W^T + b) * sigmoid(hs[t]·D)  (all h equal)
//   out[0, t, d, h] = 0 for d >= 1
//
// 8192 uniform blocks, one per timestep, NO barriers:
//   warps 1-7: zero-fill exactly 2912 float4 (= 13 x 224, all-full iterations,
//              no predicated straggler iteration).
//   warp 0   : computes the scalar (4 dot products, butterfly reduce), writes
//              the 100-float4 val row, then the 188-float4 zero tail.
// Compute-warp DRAM latency hides behind sibling fill warps in-block.
//
// R3/R5 lesson: keep the paced strided #pragma unroll 4 store-loop form;
// fully-unrolled store bursts flip ptxas into an L1tex-saturating schedule
// (+23us). R7 lesson: compute must overlap fill, never trail it.

#define HID    400
#define DEPTH  32
#define ROW4   (DEPTH * HID / 4)   // 3200 float4 per timestep
#define VAL4   (HID / 4)           // 100 float4 val row
#define ZERO4  (ROW4 - VAL4)       // 3100 float4 zero region
#define FILL4  (13 * 224)          // 2912: fill-warp share (13 full iters)
#define TAIL4  (ZERO4 - FILL4)     // 188: warp-0 tail share
#define TPB    256

__global__ void __launch_bounds__(TPB, 8)
stackmem_kernel(const float* __restrict__ hs,
                const float* __restrict__ W,
                const float* __restrict__ b,
                const float* __restrict__ Dv,
                float* __restrict__ out) {
    const int t    = blockIdx.x;
    const int wid  = threadIdx.x >> 5;
    const int lane = threadIdx.x & 31;

    float4* __restrict__ o4 =
        reinterpret_cast<float4*>(out + (size_t)t * (DEPTH * HID));

    if (wid != 0) {
        // ---------- fill warps (1..7): 224 threads, 13 full iterations ----------
        float4* __restrict__ z4 = o4 + VAL4;
        const float4 zz = make_float4(0.f, 0.f, 0.f, 0.f);
        #pragma unroll 4
        for (int i = threadIdx.x - 32; i < FILL4; i += (TPB - 32)) {
            __stcs(&z4[i], zz);
        }
        return;
    }

    // ---------- warp 0: compute val for this t ----------
    const float4* __restrict__ x4 =
        reinterpret_cast<const float4*>(hs + (size_t)t * HID);
    const float4* __restrict__ w0 = reinterpret_cast<const float4*>(W);
    const float4* __restrict__ w1 = reinterpret_cast<const float4*>(W + HID);
    const float4* __restrict__ w2 = reinterpret_cast<const float4*>(W + 2 * HID);
    const float4* __restrict__ d4 = reinterpret_cast<const float4*>(Dv);

    float a0 = 0.f, a1 = 0.f, a2 = 0.f, a3 = 0.f;
    for (int i = lane; i < VAL4; i += 32) {
        float4 x = __ldg(&x4[i]);
        float4 p;
        p = __ldg(&w0[i]); a0 += x.x*p.x + x.y*p.y + x.z*p.z + x.w*p.w;
        p = __ldg(&w1[i]); a1 += x.x*p.x + x.y*p.y + x.z*p.z + x.w*p.w;
        p = __ldg(&w2[i]); a2 += x.x*p.x + x.y*p.y + x.z*p.z + x.w*p.w;
        p = __ldg(&d4[i]); a3 += x.x*p.x + x.y*p.y + x.z*p.z + x.w*p.w;
    }

    // Butterfly reduce: every lane ends with the full sum (no broadcast).
    #pragma unroll
    for (int o = 16; o > 0; o >>= 1) {
        a0 += __shfl_xor_sync(0xFFFFFFFFu, a0, o);
        a1 += __shfl_xor_sync(0xFFFFFFFFu, a1, o);
        a2 += __shfl_xor_sync(0xFFFFFFFFu, a2, o);
        a3 += __shfl_xor_sync(0xFFFFFFFFu, a3, o);
    }

    const float l0 = a0 + __ldg(&b[0]);
    const float l1 = a1 + __ldg(&b[1]);
    const float l2 = a2 + __ldg(&b[2]);
    const float m  = fmaxf(l0, fmaxf(l1, l2));
    const float e0 = __expf(l0 - m);
    const float e1 = __expf(l1 - m);
    const float e2 = __expf(l2 - m);
    const float p0 = e0 / (e0 + e1 + e2);
    const float pv = 1.0f / (1.0f + __expf(-a3));
    const float v  = p0 * pv;
    const float4 vv = make_float4(v, v, v, v);

    // val row [0, 100)
    for (int i = lane; i < VAL4; i += 32) {
        __stcs(&o4[i], vv);
    }
    // zero tail [VAL4 + FILL4, ROW4): 188 float4
    {
        float4* __restrict__ z4 = o4 + VAL4 + FILL4;
        const float4 zz = make_float4(0.f, 0.f, 0.f, 0.f);
        #pragma unroll 4
        for (int i = lane; i < TAIL4; i += 32) {
            __stcs(&z4[i], zz);
        }
    }
}

extern "C" void kernel_launch(void* const* d_in, const int* in_sizes, int n_in,
                              void* d_out, int out_size) {
    const float* hs = (const float*)d_in[0];   // (1, T, 400)
    const float* W  = (const float*)d_in[1];   // (3, 400)
    const float* b  = (const float*)d_in[2];   // (3,)
    const float* Dv = (const float*)d_in[3];   // (1, 400)
    float* out = (float*)d_out;                // (1, T, 32, 400)

    const int T = in_sizes[0] / HID;           // 8192 (B=1)
    stackmem_kernel<<<T, TPB>>>(hs, W, b, Dv, out);
}

// round 11
// speedup vs baseline: 1.0062x; 1.0062x over previous
#include <cuda_runtime.h>

// StackMemory — FINAL: warp-specialized single-role form (R9, best at 61.5us).
//
// Reference scan only writes stack row 0 and reads row 1 (always zero), so:
//   out[0, t, 0, h] = softmax0(hs[t]·W^T + b) * sigmoid(hs[t]·D)  (all h equal)
//   out[0, t, d, h] = 0 for d >= 1
// => 433 MB mandatory traffic (419 MB writes + 13 MB reads) moved at
//    ~7.0 TB/s wall-effective — at the achievable HBM write ceiling.
//
// 8192 uniform blocks, one per timestep, NO barriers:
//   warp 0   : computes the scalar (4 length-400 dot products, butterfly
//              reduce — every lane gets the sum, no smem/broadcast) and
//              writes the 100-float4 val row.
//   warps 1-7: zero-fill the 3100-float4 d>=1 region (stride 224, paced
//              strided loop).
// The compute warp's DRAM-load latency hides behind its 7 sibling fill warps
// in-block; the grid is uniform so waves balance perfectly.
//
// Session lessons (do not perturb):
//  - R3/R5: fully-unrolled store bursts / head-peeled alignment flip ptxas
//    into an L1tex-wavefront-saturating schedule (L1 ~83%, DRAM ~54%, +23us).
//    Keep the paced '#pragma unroll 4' strided store loop exactly as-is.
//  - R7: compute work must overlap the fill stream, never trail it (+4.8us).
//  - R10: rebalancing the fill tail onto warp 0 is neutral — straggler
//    predication was already hidden by occupancy.

#define HID    400
#define DEPTH  32
#define ROW4   (DEPTH * HID / 4)   // 3200 float4 per timestep
#define VAL4   (HID / 4)           // 100 float4 val row
#define ZERO4  (ROW4 - VAL4)       // 3100 float4 zero region
#define TPB    256

__global__ void __launch_bounds__(TPB, 8)
stackmem_kernel(const float* __restrict__ hs,
                const float* __restrict__ W,
                const float* __restrict__ b,
                const float* __restrict__ Dv,
                float* __restrict__ out) {
    const int t    = blockIdx.x;
    const int wid  = threadIdx.x >> 5;
    const int lane = threadIdx.x & 31;

    float4* __restrict__ o4 =
        reinterpret_cast<float4*>(out + (size_t)t * (DEPTH * HID));

    if (wid != 0) {
        // ---------- fill warps (1..7): 224 threads over 3100 float4 ----------
        float4* __restrict__ z4 = o4 + VAL4;
        const float4 zz = make_float4(0.f, 0.f, 0.f, 0.f);
        #pragma unroll 4
        for (int i = threadIdx.x - 32; i < ZERO4; i += (TPB - 32)) {
            __stcs(&z4[i], zz);
        }
        return;
    }

    // ---------- warp 0: compute val for this t ----------
    const float4* __restrict__ x4 =
        reinterpret_cast<const float4*>(hs + (size_t)t * HID);
    const float4* __restrict__ w0 = reinterpret_cast<const float4*>(W);
    const float4* __restrict__ w1 = reinterpret_cast<const float4*>(W + HID);
    const float4* __restrict__ w2 = reinterpret_cast<const float4*>(W + 2 * HID);
    const float4* __restrict__ d4 = reinterpret_cast<const float4*>(Dv);

    float a0 = 0.f, a1 = 0.f, a2 = 0.f, a3 = 0.f;
    for (int i = lane; i < VAL4; i += 32) {
        float4 x = __ldg(&x4[i]);
        float4 p;
        p = __ldg(&w0[i]); a0 += x.x*p.x + x.y*p.y + x.z*p.z + x.w*p.w;
        p = __ldg(&w1[i]); a1 += x.x*p.x + x.y*p.y + x.z*p.z + x.w*p.w;
        p = __ldg(&w2[i]); a2 += x.x*p.x + x.y*p.y + x.z*p.z + x.w*p.w;
        p = __ldg(&d4[i]); a3 += x.x*p.x + x.y*p.y + x.z*p.z + x.w*p.w;
    }

    // Butterfly reduce: every lane ends with the full sum (no broadcast).
    #pragma unroll
    for (int o = 16; o > 0; o >>= 1) {
        a0 += __shfl_xor_sync(0xFFFFFFFFu, a0, o);
        a1 += __shfl_xor_sync(0xFFFFFFFFu, a1, o);
        a2 += __shfl_xor_sync(0xFFFFFFFFu, a2, o);
        a3 += __shfl_xor_sync(0xFFFFFFFFu, a3, o);
    }

    const float l0 = a0 + __ldg(&b[0]);
    const float l1 = a1 + __ldg(&b[1]);
    const float l2 = a2 + __ldg(&b[2]);
    const float m  = fmaxf(l0, fmaxf(l1, l2));
    const float e0 = __expf(l0 - m);
    const float e1 = __expf(l1 - m);
    const float e2 = __expf(l2 - m);
    const float p0 = e0 / (e0 + e1 + e2);
    const float pv = 1.0f / (1.0f + __expf(-a3));
    const float v  = p0 * pv;
    const float4 vv = make_float4(v, v, v, v);

    for (int i = lane; i < VAL4; i += 32) {
        __stcs(&o4[i], vv);
    }
}

extern "C" void kernel_launch(void* const* d_in, const int* in_sizes, int n_in,
                              void* d_out, int out_size) {
    const float* hs = (const float*)d_in[0];   // (1, T, 400)
    const float* W  = (const float*)d_in[1];   // (3, 400)
    const float* b  = (const float*)d_in[2];   // (3,)
    const float* Dv = (const float*)d_in[3];   // (1, 400)
    float* out = (float*)d_out;                // (1, T, 32, 400)

    const int T = in_sizes[0] / HID;           // 8192 (B=1)
    stackmem_kernel<<<T, TPB>>>(hs, W, b, Dv, out);
}